// round 1
// baseline (speedup 1.0000x reference)
#include <cuda_runtime.h>
#include <math.h>

#define BATCH 32
#define HH 1024
#define WW 1024
#define HS 128            // rows per pass2 block

// 128 MB scratch for horizontal box sums (device-global: no allocations allowed)
__device__ float g_hsum[BATCH * HH * WW];
__device__ double g_bce;
__device__ double g_inter[BATCH];
__device__ double g_union[BATCH];

__global__ void init_kernel() {
    int t = threadIdx.x;
    if (t == 0) g_bce = 0.0;
    if (t < BATCH) { g_inter[t] = 0.0; g_union[t] = 0.0; }
}

// Horizontal 31-tap box sum via per-row prefix scan. One 256-thread block per row.
// hsum[x] = pref(min(x+15,1023)) - pref(x-16)  (zero pad outside [0,1024))
__global__ void __launch_bounds__(256) hsum_kernel(const float* __restrict__ tgt) {
    const int row = blockIdx.x;                    // 0 .. BATCH*HH-1
    const float* src = tgt + (size_t)row * WW;
    float* dst = g_hsum + (size_t)row * WW;

    __shared__ float PS[WW + 32];                  // PS[16+x] = pref(0..x); guards both sides
    __shared__ float warpTot[8];
    const int tid = threadIdx.x;

    float4 v = reinterpret_cast<const float4*>(src)[tid];
    float s0 = v.x;
    float s1 = s0 + v.y;
    float s2 = s1 + v.z;
    float s3 = s2 + v.w;
    float csum = s3;

    // inclusive warp scan over per-thread chunk sums
    float ws = csum;
    #pragma unroll
    for (int d = 1; d < 32; d <<= 1) {
        float n = __shfl_up_sync(0xffffffffu, ws, d);
        if ((tid & 31) >= d) ws += n;
    }
    if ((tid & 31) == 31) warpTot[tid >> 5] = ws;
    __syncthreads();

    float base = ws - csum;                        // exclusive within warp
    const int wid = tid >> 5;
    #pragma unroll
    for (int w = 0; w < 8; ++w)
        if (w < wid) base += warpTot[w];

    PS[16 + 4 * tid + 0] = base + s0;
    PS[16 + 4 * tid + 1] = base + s1;
    PS[16 + 4 * tid + 2] = base + s2;
    PS[16 + 4 * tid + 3] = base + s3;
    if (tid < 16) {
        PS[tid] = 0.0f;                            // pref(<0) = 0
        float total = 0.f;
        #pragma unroll
        for (int w = 0; w < 8; ++w) total += warpTot[w];
        PS[16 + WW + tid] = total;                 // pref(>=W) = total
    }
    __syncthreads();

    // hsum[x] = PS[x+31] - PS[x]; interleaved ownership -> conflict-free LDS
    #pragma unroll
    for (int k = 0; k < 4; ++k) {
        int x = tid + 256 * k;
        dst[x] = PS[x + 31] - PS[x];
    }
}

// Vertical running box sum fused with all elementwise math + reductions.
// Block: 256 threads = 256 columns; covers HS rows of one batch image.
__global__ void __launch_bounds__(256) pass2_kernel(const float* __restrict__ inp,
                                                    const float* __restrict__ tgt) {
    const int b   = blockIdx.z;
    const int col = blockIdx.x * 256 + threadIdx.x;
    const int y0  = blockIdx.y * HS;
    const size_t img = (size_t)b * HH * WW;
    const float* Hp = g_hsum + img;
    const float* T  = tgt + img;
    const float* X  = inp + img;

    // warm-up: vertical window sum for row y0
    float vacc = 0.f;
    #pragma unroll
    for (int yy = y0 - 15; yy <= y0 + 15; ++yy)
        if (yy >= 0 && yy < HH) vacc += Hp[(size_t)yy * WW + col];

    float bceA = 0.f, intA = 0.f, uniA = 0.f;
    #pragma unroll 4
    for (int y = y0; y < y0 + HS; ++y) {
        const size_t idx = (size_t)y * WW + col;
        const float tv = T[idx];
        const float xv = X[idx];
        const float avg = vacc * (1.0f / 961.0f);
        const float weit = 1.0f + 5.0f * fabsf(avg - tv);
        const float ax = fabsf(xv);
        const float bce = fmaxf(xv, 0.f) - xv * tv + log1pf(__expf(-ax));
        const float p = 1.0f / (1.0f + __expf(-xv));
        bceA += bce;
        intA += p * tv * weit;
        uniA += (p + tv) * weit;
        // slide window: y -> y+1
        const int ya = y + 16, yr = y - 15;
        const float add = (ya < HH) ? Hp[(size_t)ya * WW + col] : 0.f;
        const float rem = (yr >= 0) ? Hp[(size_t)yr * WW + col] : 0.f;
        vacc += add - rem;
    }

    // block reduction (warp shuffles + smem), then double atomics
    #pragma unroll
    for (int o = 16; o > 0; o >>= 1) {
        bceA += __shfl_down_sync(0xffffffffu, bceA, o);
        intA += __shfl_down_sync(0xffffffffu, intA, o);
        uniA += __shfl_down_sync(0xffffffffu, uniA, o);
    }
    __shared__ float red[3][8];
    const int wid = threadIdx.x >> 5, lane = threadIdx.x & 31;
    if (lane == 0) { red[0][wid] = bceA; red[1][wid] = intA; red[2][wid] = uniA; }
    __syncthreads();
    if (threadIdx.x == 0) {
        double rb = 0, ri = 0, ru = 0;
        #pragma unroll
        for (int w = 0; w < 8; ++w) { rb += red[0][w]; ri += red[1][w]; ru += red[2][w]; }
        atomicAdd(&g_bce, rb);
        atomicAdd(&g_inter[b], ri);
        atomicAdd(&g_union[b], ru);
    }
}

__global__ void finalize_kernel(float* out, int n) {
    const double bce = g_bce / (double)((size_t)BATCH * HH * WW);
    double acc = 0.0;
    for (int b = 0; b < BATCH; ++b) {
        const double inter = g_inter[b];
        const double uni   = g_union[b];
        const double wiou  = 1.0 - (inter + 1.0) / (uni - inter + 1.0);
        acc += bce + wiou;   // wbce == bce exactly (scalar factors out of weighted mean)
    }
    const float r = (float)(acc / (double)BATCH);
    for (int i = threadIdx.x; i < n; i += blockDim.x) out[i] = r;
}

extern "C" void kernel_launch(void* const* d_in, const int* in_sizes, int n_in,
                              void* d_out, int out_size) {
    const float* inp = (const float*)d_in[0];   // "input"
    const float* tgt = (const float*)d_in[1];   // "target"
    float* out = (float*)d_out;

    init_kernel<<<1, 64>>>();
    hsum_kernel<<<BATCH * HH, 256>>>(tgt);
    dim3 g2(WW / 256, HH / HS, BATCH);
    pass2_kernel<<<g2, 256>>>(inp, tgt);
    finalize_kernel<<<1, 32>>>(out, out_size);
}